// round 3
// baseline (speedup 1.0000x reference)
#include <cuda_runtime.h>
#include <cstdint>

#define N_MAX 100000
#define E_MAX 1600000

// ---------------- static device scratch (no allocations allowed) -------------
__device__ float g_h[(size_t)N_MAX * 64];   // h = x @ W
__device__ float g_as[N_MAX];               // a_src per node
__device__ float g_ad[N_MAX];               // a_dst per node
__device__ int   g_count[N_MAX];            // in-degree histogram
__device__ int   g_off[N_MAX];              // exclusive offsets
__device__ int   g_cur[N_MAX];              // scatter cursors
__device__ int   g_part[256];               // scan block partials
__device__ int   g_srt[E_MAX];              // edge sources sorted by dst
__device__ float g_rsum[64];                // sum over nodes of relu(agg)
__device__ int   g_is64;                    // 1 if edge buffer is int64 words

// ---------------- kernel A: detect edge-index storage width ------------------
// int64 values < 2^31 have all-zero odd words (little-endian). Genuine int32
// node-id data makes 2048 consecutive zero odd-words impossible in practice.
__global__ void k_detect(const int* __restrict__ ei32, int E) {
    int nz = 0;
    int samples = 2048;
    if (samples > E) samples = E;
    for (int e = threadIdx.x; e < samples; e += 32)
        nz |= ei32[2 * e + 1];
#pragma unroll
    for (int o = 16; o > 0; o >>= 1)
        nz |= __shfl_xor_sync(0xffffffffu, nz, o);
    if (threadIdx.x == 0) g_is64 = (nz == 0) ? 1 : 0;
}

// edge decode helpers: layout is [2, E]; row 0 = src, row 1 = dst.
__device__ __forceinline__ int edge_src(const int* ei32, int E, int e) {
    return g_is64 ? ei32[2 * (size_t)e] : ei32[e];
}
__device__ __forceinline__ int edge_dst(const int* ei32, int E, int e) {
    return g_is64 ? ei32[2 * ((size_t)E + e)] : ei32[(size_t)E + e];
}

// ---------------- kernel 0: zero scratch -------------------------------------
__global__ void k_zero(int n) {
    int i = blockIdx.x * blockDim.x + threadIdx.x;
    if (i < n) g_count[i] = 0;
    if (i < 64) g_rsum[i] = 0.f;
}

// ---------------- kernel 1: GEMM h = x@W, plus a_src/a_dst -------------------
// One node per thread; W (128x64 fp32 = 32KB) staged in smem, read via
// warp-uniform broadcast LDS.128 (conflict-free). 64 fp32 accumulators/thread.
__global__ void __launch_bounds__(128) k_gemm(
    const float* __restrict__ x, const float* __restrict__ W,
    const float* __restrict__ att_s, const float* __restrict__ att_d, int n)
{
    __shared__ float4 Ws[2048];      // 128 rows x 16 float4
    __shared__ float atts[64], attd[64];
    int t = threadIdx.x;
    for (int i = t; i < 2048; i += 128) Ws[i] = ((const float4*)W)[i];
    if (t < 64) { atts[t] = att_s[t]; attd[t] = att_d[t]; }
    __syncthreads();

    int node = blockIdx.x * 128 + t;
    if (node >= n) return;

    const float4* xr = (const float4*)(x + (size_t)node * 128);
    float acc[64];
#pragma unroll
    for (int c = 0; c < 64; c++) acc[c] = 0.f;

#pragma unroll 1
    for (int k4 = 0; k4 < 32; k4++) {
        float4 xq = xr[k4];
        float xa[4];
        xa[0] = xq.x; xa[1] = xq.y; xa[2] = xq.z; xa[3] = xq.w;
#pragma unroll
        for (int i = 0; i < 4; i++) {
            float xv = xa[i];
            int kk = k4 * 4 + i;
#pragma unroll
            for (int c4 = 0; c4 < 16; c4++) {
                float4 w = Ws[kk * 16 + c4];   // broadcast: all lanes same addr
                acc[c4 * 4 + 0] += xv * w.x;
                acc[c4 * 4 + 1] += xv * w.y;
                acc[c4 * 4 + 2] += xv * w.z;
                acc[c4 * 4 + 3] += xv * w.w;
            }
        }
    }

    float4* ho = (float4*)(g_h + (size_t)node * 64);
    float s = 0.f, d = 0.f;
#pragma unroll
    for (int c4 = 0; c4 < 16; c4++) {
        float4 v = make_float4(acc[c4*4+0], acc[c4*4+1], acc[c4*4+2], acc[c4*4+3]);
        ho[c4] = v;
        s += v.x * atts[c4*4+0] + v.y * atts[c4*4+1] + v.z * atts[c4*4+2] + v.w * atts[c4*4+3];
        d += v.x * attd[c4*4+0] + v.y * attd[c4*4+1] + v.z * attd[c4*4+2] + v.w * attd[c4*4+3];
    }
    g_as[node] = s;
    g_ad[node] = d;
}

// ---------------- kernel 2: dst histogram ------------------------------------
__global__ void k_hist(const int* __restrict__ ei32, int E, int n) {
    int e = blockIdx.x * blockDim.x + threadIdx.x;
    if (e < E) {
        int i = edge_dst(ei32, E, e);
        if ((unsigned)i < (unsigned)n)      // defensive: never true if decode ok
            atomicAdd(&g_count[i], 1);
    }
}

// ---------------- kernels 3-5: two-level exclusive scan ----------------------
__global__ void k_scan1(int n) {
    __shared__ int sm[1024];
    int tid = threadIdx.x;
    int gid = blockIdx.x * 1024 + tid;
    int v = (gid < n) ? g_count[gid] : 0;
    sm[tid] = v;
    __syncthreads();
    for (int off = 1; off < 1024; off <<= 1) {
        int add = 0;
        if (tid >= off) add = sm[tid - off];
        __syncthreads();
        sm[tid] += add;
        __syncthreads();
    }
    int incl = sm[tid];
    if (gid < n) g_off[gid] = incl - v;           // block-local exclusive
    if (tid == 1023) g_part[blockIdx.x] = incl;   // block total
}

__global__ void k_scan2(int nb) {
    __shared__ int sm[256];
    int tid = threadIdx.x;  // 256 threads
    int v = (tid < nb) ? g_part[tid] : 0;
    sm[tid] = v;
    __syncthreads();
    for (int off = 1; off < 256; off <<= 1) {
        int add = 0;
        if (tid >= off) add = sm[tid - off];
        __syncthreads();
        sm[tid] += add;
        __syncthreads();
    }
    if (tid < nb) g_part[tid] = sm[tid] - v;      // exclusive
}

__global__ void k_scan3(int n) {
    int i = blockIdx.x * blockDim.x + threadIdx.x;
    if (i < n) {
        int off = g_off[i] + g_part[i >> 10];
        g_off[i] = off;
        g_cur[i] = off;
    }
}

// ---------------- kernel 6: scatter edges binned by dst ----------------------
__global__ void k_scatter(const int* __restrict__ ei32, int E, int n) {
    int e = blockIdx.x * blockDim.x + threadIdx.x;
    if (e < E) {
        int j = edge_src(ei32, E, e);
        int i = edge_dst(ei32, E, e);
        if ((unsigned)i < (unsigned)n && (unsigned)j < (unsigned)n) {
            int p = atomicAdd(&g_cur[i], 1);
            g_srt[p] = j;
        }
    }
}

// ---------------- kernel 7: warp-per-node softmax aggregation ----------------
// acc = sum_j e_ij * h[j]  (incl. self loop), denom = sum e_ij (no max-shift:
// logits bounded ~|8|, exp safe in fp32; softmax shift-invariant).
// Then relu(acc/denom + bias) reduced into g_rsum.
__global__ void __launch_bounds__(256) k_agg(const float* __restrict__ bias, int n) {
    __shared__ float rs[64];
    int t = threadIdx.x;
    if (t < 64) rs[t] = 0.f;
    __syncthreads();

    int warp = (blockIdx.x * 256 + t) >> 5;
    int l = t & 31;
    if (warp < n) {
        int i = warp;
        int start = g_off[i];
        int len = g_count[i];
        float adi = g_ad[i];
        float acc0 = 0.f, acc1 = 0.f, den = 0.f;
        for (int k = 0; k < len; k++) {
            int j = g_srt[start + k];                       // broadcast load
            float v = g_as[j] + adi;                        // broadcast load
            v = v > 0.f ? v : 0.2f * v;
            float w = __expf(v);
            den += w;
            const float* hj = g_h + (size_t)j * 64;
            acc0 += w * hj[l];                              // coalesced 128B
            acc1 += w * hj[l + 32];
        }
        // self loop
        {
            float v = g_as[i] + adi;
            v = v > 0.f ? v : 0.2f * v;
            float w = __expf(v);
            den += w;
            const float* hi = g_h + (size_t)i * 64;
            acc0 += w * hi[l];
            acc1 += w * hi[l + 32];
        }
        float inv = 1.f / den;
        float r0 = acc0 * inv + bias[l];        r0 = r0 > 0.f ? r0 : 0.f;
        float r1 = acc1 * inv + bias[l + 32];   r1 = r1 > 0.f ? r1 : 0.f;
        atomicAdd(&rs[l], r0);
        atomicAdd(&rs[l + 32], r1);
    }
    __syncthreads();
    if (t < 64) atomicAdd(&g_rsum[t], rs[t]);
}

// ---------------- kernel 8: out = (rsum/N) @ W_lin + b_lin -------------------
__global__ void k_final(const float* __restrict__ Wl, const float* __restrict__ bl,
                        float* __restrict__ out, float invn) {
    int o = threadIdx.x;   // 64 threads
    float s = 0.f;
#pragma unroll 4
    for (int c = 0; c < 64; c++) s += g_rsum[c] * Wl[c * 64 + o];
    out[o] = s * invn + bl[o];
}

// ---------------- launcher ---------------------------------------------------
extern "C" void kernel_launch(void* const* d_in, const int* in_sizes, int n_in,
                              void* d_out, int out_size) {
    const float* x    = (const float*)d_in[0];
    const int*   ei32 = (const int*)d_in[1];     // int32 OR int64 words (probed)
    const float* W    = (const float*)d_in[2];
    const float* atts = (const float*)d_in[3];
    const float* attd = (const float*)d_in[4];
    const float* bc   = (const float*)d_in[5];
    const float* Wl   = (const float*)d_in[6];
    const float* bl   = (const float*)d_in[7];
    float*       out  = (float*)d_out;

    int n = in_sizes[0] / 128;   // nodes
    int E = in_sizes[1] / 2;     // edges ([2, E] layout, element count = 2E)
    if (n > N_MAX) n = N_MAX;    // scratch capacity guard
    if (E > E_MAX) E = E_MAX;

    int nb1 = (n + 1023) / 1024;

    k_detect <<<1, 32>>>(ei32, E);
    k_zero   <<<(n + 255) / 256, 256>>>(n);
    k_gemm   <<<(n + 127) / 128, 128>>>(x, W, atts, attd, n);
    k_hist   <<<(E + 255) / 256, 256>>>(ei32, E, n);
    k_scan1  <<<nb1, 1024>>>(n);
    k_scan2  <<<1, 256>>>(nb1);
    k_scan3  <<<(n + 255) / 256, 256>>>(n);
    k_scatter<<<(E + 255) / 256, 256>>>(ei32, E, n);
    k_agg    <<<(n + 7) / 8, 256>>>(bc, n);
    k_final  <<<1, 64>>>(Wl, bl, out, 1.f / (float)n);
}